// round 11
// baseline (speedup 1.0000x reference)
#include <cuda_runtime.h>

// Problem constants
#define N_ROWS   1344              // B*C = 64*21
#define R_WIN    32                // windows per row (L/MAX_PL = 1024/32)
#define NWIN     (N_ROWS * R_WIN)  // 43008
#define DM       512               // D_MODEL
#define TGT      4                 // MAX_PL/MIN_PL
#define PE_LEN   128               // R_WIN * TGT
#define MAIN_OUT ((long long)N_ROWS * PE_LEN * DM)  // 88080384
#define CLS_BLOCKS (NWIN / 128)    // 336 blocks x 128 threads (1 thread/window)

typedef unsigned long long u64;

// f32x2 packed helpers (sm_103a FFMA2 — PTX-only form).
__device__ __forceinline__ u64 fma2(u64 a, u64 b, u64 c) {
    u64 d; asm("fma.rn.f32x2 %0, %1, %2, %3;" : "=l"(d) : "l"(a), "l"(b), "l"(c));
    return d;
}
__device__ __forceinline__ u64 mul2(u64 a, u64 b) {
    u64 d; asm("mul.rn.f32x2 %0, %1, %2;" : "=l"(d) : "l"(a), "l"(b));
    return d;
}
__device__ __forceinline__ u64 add2(u64 a, u64 b) {
    u64 d; asm("add.rn.f32x2 %0, %1, %2;" : "=l"(d) : "l"(a), "l"(b));
    return d;
}
__device__ __forceinline__ float hadd2(u64 a) {
    float lo, hi;
    asm("mov.b64 {%0, %1}, %2;" : "=f"(lo), "=f"(hi) : "l"(a));
    return lo + hi;
}

// Scratch: packed preds, 2 bits per window via two ballot words per n.
__device__ uint2 g_predpk[N_ROWS];

// ---------------------------------------------------------------------------
// Kernel 1: classifier + tail fill. One thread per window, weights staged in
// smem (broadcast LDS inner loop). Each warp covers one n's 32 windows ->
// preds packed via two ballots, one uint2 store per n.
// ---------------------------------------------------------------------------
__global__ void __launch_bounds__(128)
pre_kernel(const float* __restrict__ x,
           const float* __restrict__ w1,
           const float* __restrict__ b1,
           const float* __restrict__ w2,
           const float* __restrict__ b2,
           float* __restrict__ out,
           long long tail_start, long long total) {
    int bid = blockIdx.x;
    if (bid >= CLS_BLOCKS) {
        long long i = tail_start + (long long)(bid - CLS_BLOCKS) * 128 + threadIdx.x;
        if (i < total) out[i] = 21.0f;   // reference returns (x_patch, C=21)
        return;
    }

    __shared__ __align__(16) float s_w1[64 * 32];   // 8 KB
    __shared__ __align__(16) float s_w2[192];
    __shared__ float s_b1[64];
    __shared__ float s_b2[3];

    const int tid = threadIdx.x;

    // Cooperative coalesced staging.
    {
        const float4* g = (const float4*)w1;
        float4* sm = (float4*)s_w1;
#pragma unroll
        for (int i = 0; i < 4; i++) sm[tid + 128 * i] = g[tid + 128 * i];
        if (tid < 48) ((float4*)s_w2)[tid] = ((const float4*)w2)[tid];
        if (tid < 64) s_b1[tid] = b1[tid];
        if (tid < 3)  s_b2[tid] = b2[tid];
    }
    __syncthreads();

    const int w = bid * 128 + tid;

    const float4* xw = (const float4*)(x + (size_t)w * 32);
    float4 xv[8];
#pragma unroll
    for (int i = 0; i < 8; i++) xv[i] = xw[i];

    float l0 = s_b2[0], l1 = s_b2[1], l2 = s_b2[2];

#pragma unroll 4
    for (int h = 0; h < 64; h++) {
        const float4* wr = (const float4*)(s_w1 + h * 32);   // broadcast LDS
        float a0 = 0.f, a1 = 0.f, a2 = 0.f, a3 = 0.f;
#pragma unroll
        for (int i = 0; i < 8; i++) {
            float4 wv = wr[i];
            a0 = fmaf(wv.x, xv[i].x, a0);
            a1 = fmaf(wv.y, xv[i].y, a1);
            a2 = fmaf(wv.z, xv[i].z, a2);
            a3 = fmaf(wv.w, xv[i].w, a3);
        }
        float hv = s_b1[h] + ((a0 + a1) + (a2 + a3));
        hv = fmaxf(hv, 0.0f);
        l0 = fmaf(s_w2[h], hv, l0);
        l1 = fmaf(s_w2[64 + h], hv, l1);
        l2 = fmaf(s_w2[128 + h], hv, l2);
    }

    int p = 0;
    float m = l0;
    if (l1 > m) { m = l1; p = 1; }   // strict > = first-max (jnp.argmax)
    if (l2 > m) { m = l2; p = 2; }

    // Pack: warp = one n (lane = window). Two ballots -> uint2.
    unsigned pb0 = __ballot_sync(0xffffffffu, p & 1);
    unsigned pb1 = __ballot_sync(0xffffffffu, p & 2);
    if ((tid & 31) == 0) g_predpk[w >> 5] = make_uint2(pb0, pb1);
}

// ---------------------------------------------------------------------------
// Kernel 2: embedding + repeat + PE + store.
// R9 mapping, but the per-window x reads are CONVERGED GLOBAL LOADS instead
// of smem broadcasts: a converged LDG dedupes to one 16B sector/wavefront,
// whereas LDS.128 always moves 512B/warp through the crossbar (the measured
// 84us wall). No smem, no __syncthreads. Preds come packed via ballots.
// ---------------------------------------------------------------------------
__global__ void __launch_bounds__(256, 2)
emb_kernel(const float* __restrict__ x,
           const float* __restrict__ we0,   // [512][8]
           const float* __restrict__ we1,   // [512][16]
           const float* __restrict__ we2,   // [512][32]
           float* __restrict__ out) {
    const int tid  = threadIdx.x;
    const int n    = blockIdx.x >> 1;
    const int dblk = (blockIdx.x & 1) << 8;
    const int d    = dblk + tid;

    // Weight cache as packed pairs.
    u64 w0r[4], w1r[8], w2r[16];
    {
        const ulonglong2* p0 = (const ulonglong2*)(we0 + d * 8);
#pragma unroll
        for (int i = 0; i < 2; i++) { ulonglong2 v = p0[i]; w0r[2*i] = v.x; w0r[2*i+1] = v.y; }
        const ulonglong2* p1 = (const ulonglong2*)(we1 + d * 16);
#pragma unroll
        for (int i = 0; i < 4; i++) { ulonglong2 v = p1[i]; w1r[2*i] = v.x; w1r[2*i+1] = v.y; }
        const ulonglong2* p2 = (const ulonglong2*)(we2 + d * 32);
#pragma unroll
        for (int i = 0; i < 8; i++) { ulonglong2 v = p2[i]; w2r[2*i] = v.x; w2r[2*i+1] = v.y; }
    }

    // Packed preds for this n (converged scalar load).
    const uint2 pb = g_predpk[n];

    // PE setup: step sines/cosines for k = 1..4 steps of Delta.
    const float kLn = -9.21034037197618f / (float)DM;   // -ln(10000)/512
    float delta = expf((float)(d & ~1) * kLn);
    float s1, c1;
    sincosf(delta, &s1, &c1);
    float s2 = 2.0f * s1 * c1;
    float c2 = fmaf(c1, c1, -s1 * s1);
    float s3 = fmaf(s1, c2, c1 * s2);
    float c3 = fmaf(c1, c2, -s1 * s2);
    float s4 = 2.0f * s2 * c2;
    float c4 = fmaf(c2, c2, -s2 * s2);
    // Phase-shifted state: odd d computes cos via sin(x + pi/2).
    float s = (d & 1) ? 1.0f : 0.0f;
    float c = (d & 1) ? 0.0f : 1.0f;

    const float* xrow = x + (size_t)n * 1024;
    float* o = out + (size_t)n * (PE_LEN * DM) + d;

#pragma unroll 1
    for (int w = 0; w < R_WIN; w++) {
        int pred = ((pb.x >> w) & 1u) | (((pb.y >> w) & 1u) << 1);

        // Converged global loads of the 32-float window (1 sector/wavefront).
        const ulonglong2* xq2 = (const ulonglong2*)(xrow + w * 32);
        u64 xv[16];
#pragma unroll
        for (int i = 0; i < 8; i++) {
            ulonglong2 v = __ldg(&xq2[i]);
            xv[2*i] = v.x; xv[2*i+1] = v.y;
        }

        float v0, v1, v2, v3;
        if (pred == 0) {
            // 4 patches of 8 floats; repeat idx = [0,1,2,3]
            float acc[4];
#pragma unroll
            for (int k = 0; k < 4; k++) {
                u64 a = mul2(w0r[0], xv[4*k]);
                a = fma2(w0r[1], xv[4*k+1], a);
                a = fma2(w0r[2], xv[4*k+2], a);
                a = fma2(w0r[3], xv[4*k+3], a);
                acc[k] = hadd2(a);
            }
            v0 = acc[0]; v1 = acc[1]; v2 = acc[2]; v3 = acc[3];
        } else if (pred == 1) {
            // 2 patches of 16 floats; repeat idx = [0,0,0,1]
            u64 a0 = mul2(w1r[0], xv[0]);
            u64 a1 = mul2(w1r[1], xv[1]);
            a0 = fma2(w1r[2], xv[2], a0);
            a1 = fma2(w1r[3], xv[3], a1);
            a0 = fma2(w1r[4], xv[4], a0);
            a1 = fma2(w1r[5], xv[5], a1);
            a0 = fma2(w1r[6], xv[6], a0);
            a1 = fma2(w1r[7], xv[7], a1);
            float a = hadd2(add2(a0, a1));

            u64 b0 = mul2(w1r[0], xv[8]);
            u64 b1 = mul2(w1r[1], xv[9]);
            b0 = fma2(w1r[2], xv[10], b0);
            b1 = fma2(w1r[3], xv[11], b1);
            b0 = fma2(w1r[4], xv[12], b0);
            b1 = fma2(w1r[5], xv[13], b1);
            b0 = fma2(w1r[6], xv[14], b0);
            b1 = fma2(w1r[7], xv[15], b1);
            float b = hadd2(add2(b0, b1));
            v0 = a; v1 = a; v2 = a; v3 = b;
        } else {
            // 1 patch of 32 floats -> replicated 4x
            u64 a0 = mul2(w2r[0], xv[0]);
            u64 a1 = mul2(w2r[1], xv[1]);
            u64 a2 = mul2(w2r[2], xv[2]);
            u64 a3 = mul2(w2r[3], xv[3]);
#pragma unroll
            for (int i = 4; i < 16; i += 4) {
                a0 = fma2(w2r[i],   xv[i],   a0);
                a1 = fma2(w2r[i+1], xv[i+1], a1);
                a2 = fma2(w2r[i+2], xv[i+2], a2);
                a3 = fma2(w2r[i+3], xv[i+3], a3);
            }
            float cc = hadd2(add2(add2(a0, a1), add2(a2, a3)));
            v0 = cc; v1 = cc; v2 = cc; v3 = cc;
        }

        // PE: independent rotations from the window-base angle, add folded.
        o[0 * DM] = v0 + s;
        o[1 * DM] = fmaf(s, c1, fmaf(c, s1, v1));
        o[2 * DM] = fmaf(s, c2, fmaf(c, s2, v2));
        o[3 * DM] = fmaf(s, c3, fmaf(c, s3, v3));
        // Advance base angle by 4*Delta.
        float ns = fmaf(s, c4, c * s4);
        c = fmaf(c, c4, -s * s4);
        s = ns;

        o += TGT * DM;
    }
}

extern "C" void kernel_launch(void* const* d_in, const int* in_sizes, int n_in,
                              void* d_out, int out_size) {
    const float* x   = (const float*)d_in[0];
    const float* w1  = (const float*)d_in[1];
    const float* b1  = (const float*)d_in[2];
    const float* w2  = (const float*)d_in[3];
    const float* b2  = (const float*)d_in[4];
    const float* we0 = (const float*)d_in[5];
    const float* we1 = (const float*)d_in[6];
    const float* we2 = (const float*)d_in[7];
    float* out = (float*)d_out;

    long long total = (long long)out_size;
    long long tail  = (total > MAIN_OUT) ? (total - MAIN_OUT) : 0;
    int tail_blocks = (int)((tail + 127) / 128);

    pre_kernel<<<CLS_BLOCKS + tail_blocks, 128>>>(x, w1, b1, w2, b2,
                                                  out, MAIN_OUT, total);
    emb_kernel<<<N_ROWS * 2, 256>>>(x, we0, we1, we2, out);
}

// round 12
// speedup vs baseline: 2.0752x; 2.0752x over previous
#include <cuda_runtime.h>

// Problem constants
#define N_ROWS   1344              // B*C = 64*21
#define R_WIN    32                // windows per row (L/MAX_PL = 1024/32)
#define NWIN     (N_ROWS * R_WIN)  // 43008
#define DM       512               // D_MODEL
#define TGT      4                 // MAX_PL/MIN_PL
#define PE_LEN   128               // R_WIN * TGT
#define MAIN_OUT ((long long)N_ROWS * PE_LEN * DM)  // 88080384
#define CLS_BLOCKS (NWIN / 128)    // 336 blocks x 128 threads (1 thread/window)

typedef unsigned long long u64;

// f32x2 packed helpers (sm_103a FFMA2 — PTX-only form).
__device__ __forceinline__ u64 fma2(u64 a, u64 b, u64 c) {
    u64 d; asm("fma.rn.f32x2 %0, %1, %2, %3;" : "=l"(d) : "l"(a), "l"(b), "l"(c));
    return d;
}
__device__ __forceinline__ u64 mul2(u64 a, u64 b) {
    u64 d; asm("mul.rn.f32x2 %0, %1, %2;" : "=l"(d) : "l"(a), "l"(b));
    return d;
}
__device__ __forceinline__ u64 add2(u64 a, u64 b) {
    u64 d; asm("add.rn.f32x2 %0, %1, %2;" : "=l"(d) : "l"(a), "l"(b));
    return d;
}
__device__ __forceinline__ float hadd2(u64 a) {
    float lo, hi;
    asm("mov.b64 {%0, %1}, %2;" : "=f"(lo), "=f"(hi) : "l"(a));
    return lo + hi;
}

// Scratch: packed preds, 2 bits per window via two ballot words per n.
__device__ uint2 g_predpk[N_ROWS];

// ---------------------------------------------------------------------------
// Kernel 1: classifier + tail fill (R9's proven version, ballot-packed preds).
// ---------------------------------------------------------------------------
__global__ void __launch_bounds__(128)
pre_kernel(const float* __restrict__ x,
           const float* __restrict__ w1,
           const float* __restrict__ b1,
           const float* __restrict__ w2,
           const float* __restrict__ b2,
           float* __restrict__ out,
           long long tail_start, long long total) {
    int bid = blockIdx.x;
    if (bid >= CLS_BLOCKS) {
        long long i = tail_start + (long long)(bid - CLS_BLOCKS) * 128 + threadIdx.x;
        if (i < total) out[i] = 21.0f;   // reference returns (x_patch, C=21)
        return;
    }

    __shared__ __align__(16) float s_w1[64 * 32];   // 8 KB
    __shared__ __align__(16) float s_w2[192];
    __shared__ float s_b1[64];
    __shared__ float s_b2[3];

    const int tid = threadIdx.x;

    {
        const float4* g = (const float4*)w1;
        float4* sm = (float4*)s_w1;
#pragma unroll
        for (int i = 0; i < 4; i++) sm[tid + 128 * i] = g[tid + 128 * i];
        if (tid < 48) ((float4*)s_w2)[tid] = ((const float4*)w2)[tid];
        if (tid < 64) s_b1[tid] = b1[tid];
        if (tid < 3)  s_b2[tid] = b2[tid];
    }
    __syncthreads();

    const int w = bid * 128 + tid;

    const float4* xw = (const float4*)(x + (size_t)w * 32);
    float4 xv[8];
#pragma unroll
    for (int i = 0; i < 8; i++) xv[i] = xw[i];

    float l0 = s_b2[0], l1 = s_b2[1], l2 = s_b2[2];

#pragma unroll 4
    for (int h = 0; h < 64; h++) {
        const float4* wr = (const float4*)(s_w1 + h * 32);   // broadcast LDS
        float a0 = 0.f, a1 = 0.f, a2 = 0.f, a3 = 0.f;
#pragma unroll
        for (int i = 0; i < 8; i++) {
            float4 wv = wr[i];
            a0 = fmaf(wv.x, xv[i].x, a0);
            a1 = fmaf(wv.y, xv[i].y, a1);
            a2 = fmaf(wv.z, xv[i].z, a2);
            a3 = fmaf(wv.w, xv[i].w, a3);
        }
        float hv = s_b1[h] + ((a0 + a1) + (a2 + a3));
        hv = fmaxf(hv, 0.0f);
        l0 = fmaf(s_w2[h], hv, l0);
        l1 = fmaf(s_w2[64 + h], hv, l1);
        l2 = fmaf(s_w2[128 + h], hv, l2);
    }

    int p = 0;
    float m = l0;
    if (l1 > m) { m = l1; p = 1; }   // strict > = first-max (jnp.argmax)
    if (l2 > m) { m = l2; p = 2; }

    unsigned pb0 = __ballot_sync(0xffffffffu, p & 1);
    unsigned pb1 = __ballot_sync(0xffffffffu, p & 2);
    if ((tid & 31) == 0) g_predpk[w >> 5] = make_uint2(pb0, pb1);
}

// ---------------------------------------------------------------------------
// Kernel 2: embedding + repeat + PE + store — TWO dims per thread (2t, 2t+1).
// Halves the warps per n (8 vs 16) and therefore the smem-crossbar broadcast
// traffic per output dim (the measured 84us wall in R9). The even/odd pair
// shares ONE PE rotation state (even needs sin, odd needs cos). Adjacent
// dims -> one STG.64 per position. 128 thr/block, natural regs ~175 (<255,
// no spill), 2 CTAs/SM.
// ---------------------------------------------------------------------------
__global__ void __launch_bounds__(128)
emb_kernel(const float* __restrict__ x,
           const float* __restrict__ we0,   // [512][8]
           const float* __restrict__ we1,   // [512][16]
           const float* __restrict__ we2,   // [512][32]
           float* __restrict__ out) {
    __shared__ __align__(16) float s_x[R_WIN * 32];   // 4 KB

    const int tid  = threadIdx.x;
    const int n    = blockIdx.x >> 1;
    const int dblk = (blockIdx.x & 1) << 8;
    const int d0   = dblk + 2 * tid;     // even dim
    // odd dim = d0 + 1

    // Weight cache for BOTH dims, packed pairs. [j][...] j=0 even, j=1 odd.
    u64 w0r[2][4], w1r[2][8], w2r[2][16];
#pragma unroll
    for (int j = 0; j < 2; j++) {
        int dd = d0 + j;
        const ulonglong2* p0 = (const ulonglong2*)(we0 + dd * 8);
#pragma unroll
        for (int i = 0; i < 2; i++) { ulonglong2 v = p0[i]; w0r[j][2*i] = v.x; w0r[j][2*i+1] = v.y; }
        const ulonglong2* p1 = (const ulonglong2*)(we1 + dd * 16);
#pragma unroll
        for (int i = 0; i < 4; i++) { ulonglong2 v = p1[i]; w1r[j][2*i] = v.x; w1r[j][2*i+1] = v.y; }
        const ulonglong2* p2 = (const ulonglong2*)(we2 + dd * 32);
#pragma unroll
        for (int i = 0; i < 8; i++) { ulonglong2 v = p2[i]; w2r[j][2*i] = v.x; w2r[j][2*i+1] = v.y; }
    }

    // Cooperative x-row staging (128 threads x 2 float4 = 1024 floats).
    {
        const float4* xg = (const float4*)(x + (size_t)n * 1024);
        ((float4*)s_x)[tid]       = xg[tid];
        ((float4*)s_x)[tid + 128] = xg[tid + 128];
    }
    const uint2 pb = g_predpk[n];

    // PE setup — ONE frequency for the pair (d0 even).
    const float kLn = -9.21034037197618f / (float)DM;   // -ln(10000)/512
    float delta = expf((float)d0 * kLn);
    float s1, c1;
    sincosf(delta, &s1, &c1);
    float s2 = 2.0f * s1 * c1;
    float c2 = fmaf(c1, c1, -s1 * s1);
    float s3 = fmaf(s1, c2, c1 * s2);
    float c3 = fmaf(c1, c2, -s1 * s2);
    float s4 = 2.0f * s2 * c2;
    float c4 = fmaf(c2, c2, -s2 * s2);
    float s = 0.0f, c = 1.0f;           // state at pos 0

    __syncthreads();

    float* o = out + (size_t)n * (PE_LEN * DM) + d0;

#pragma unroll 1
    for (int w = 0; w < R_WIN; w++) {
        int pred = ((pb.x >> w) & 1u) | (((pb.y >> w) & 1u) << 1);

        const ulonglong2* xq2 = (const ulonglong2*)(s_x + w * 32);
        u64 xv[16];
#pragma unroll
        for (int i = 0; i < 8; i++) { ulonglong2 v = xq2[i]; xv[2*i] = v.x; xv[2*i+1] = v.y; }

        // vE[k] (even dim), vO[k] (odd dim) for positions k=0..3.
        float vE0, vE1, vE2, vE3, vO0, vO1, vO2, vO3;
        if (pred == 0) {
            // 4 patches of 8 floats; repeat idx = [0,1,2,3]
            float aE[4], aO[4];
#pragma unroll
            for (int k = 0; k < 4; k++) {
                u64 aa = mul2(w0r[0][0], xv[4*k]);
                aa = fma2(w0r[0][1], xv[4*k+1], aa);
                aa = fma2(w0r[0][2], xv[4*k+2], aa);
                aa = fma2(w0r[0][3], xv[4*k+3], aa);
                aE[k] = hadd2(aa);
                u64 bb = mul2(w0r[1][0], xv[4*k]);
                bb = fma2(w0r[1][1], xv[4*k+1], bb);
                bb = fma2(w0r[1][2], xv[4*k+2], bb);
                bb = fma2(w0r[1][3], xv[4*k+3], bb);
                aO[k] = hadd2(bb);
            }
            vE0 = aE[0]; vE1 = aE[1]; vE2 = aE[2]; vE3 = aE[3];
            vO0 = aO[0]; vO1 = aO[1]; vO2 = aO[2]; vO3 = aO[3];
        } else if (pred == 1) {
            // 2 patches of 16 floats; repeat idx = [0,0,0,1]
            float hE[2], hO[2];
#pragma unroll
            for (int half = 0; half < 2; half++) {
                const u64* xh = xv + 8 * half;
                u64 a0 = mul2(w1r[0][0], xh[0]);
                u64 a1 = mul2(w1r[0][1], xh[1]);
                u64 b0 = mul2(w1r[1][0], xh[0]);
                u64 b1 = mul2(w1r[1][1], xh[1]);
#pragma unroll
                for (int i = 2; i < 8; i += 2) {
                    a0 = fma2(w1r[0][i],   xh[i],   a0);
                    a1 = fma2(w1r[0][i+1], xh[i+1], a1);
                    b0 = fma2(w1r[1][i],   xh[i],   b0);
                    b1 = fma2(w1r[1][i+1], xh[i+1], b1);
                }
                hE[half] = hadd2(add2(a0, a1));
                hO[half] = hadd2(add2(b0, b1));
            }
            vE0 = hE[0]; vE1 = hE[0]; vE2 = hE[0]; vE3 = hE[1];
            vO0 = hO[0]; vO1 = hO[0]; vO2 = hO[0]; vO3 = hO[1];
        } else {
            // 1 patch of 32 floats -> replicated 4x
            u64 a0 = mul2(w2r[0][0], xv[0]);
            u64 a1 = mul2(w2r[0][1], xv[1]);
            u64 b0 = mul2(w2r[1][0], xv[0]);
            u64 b1 = mul2(w2r[1][1], xv[1]);
#pragma unroll
            for (int i = 2; i < 16; i += 2) {
                a0 = fma2(w2r[0][i],   xv[i],   a0);
                a1 = fma2(w2r[0][i+1], xv[i+1], a1);
                b0 = fma2(w2r[1][i],   xv[i],   b0);
                b1 = fma2(w2r[1][i+1], xv[i+1], b1);
            }
            float ce = hadd2(add2(a0, a1));
            float co = hadd2(add2(b0, b1));
            vE0 = ce; vE1 = ce; vE2 = ce; vE3 = ce;
            vO0 = co; vO1 = co; vO2 = co; vO3 = co;
        }

        // PE: one rotation state serves both dims (even: +sin, odd: +cos).
        float sn1 = fmaf(s, c1, c * s1), co1 = fmaf(c, c1, -s * s1);
        float sn2 = fmaf(s, c2, c * s2), co2 = fmaf(c, c2, -s * s2);
        float sn3 = fmaf(s, c3, c * s3), co3 = fmaf(c, c3, -s * s3);

        *(float2*)(o + 0 * DM) = make_float2(vE0 + s,   vO0 + c);
        *(float2*)(o + 1 * DM) = make_float2(vE1 + sn1, vO1 + co1);
        *(float2*)(o + 2 * DM) = make_float2(vE2 + sn2, vO2 + co2);
        *(float2*)(o + 3 * DM) = make_float2(vE3 + sn3, vO3 + co3);

        // Advance base angle by 4*Delta.
        float ns = fmaf(s, c4, c * s4);
        c = fmaf(c, c4, -s * s4);
        s = ns;

        o += TGT * DM;
    }
}

extern "C" void kernel_launch(void* const* d_in, const int* in_sizes, int n_in,
                              void* d_out, int out_size) {
    const float* x   = (const float*)d_in[0];
    const float* w1  = (const float*)d_in[1];
    const float* b1  = (const float*)d_in[2];
    const float* w2  = (const float*)d_in[3];
    const float* b2  = (const float*)d_in[4];
    const float* we0 = (const float*)d_in[5];
    const float* we1 = (const float*)d_in[6];
    const float* we2 = (const float*)d_in[7];
    float* out = (float*)d_out;

    long long total = (long long)out_size;
    long long tail  = (total > MAIN_OUT) ? (total - MAIN_OUT) : 0;
    int tail_blocks = (int)((tail + 127) / 128);

    pre_kernel<<<CLS_BLOCKS + tail_blocks, 128>>>(x, w1, b1, w2, b2,
                                                  out, MAIN_OUT, total);
    emb_kernel<<<N_ROWS * 2, 128>>>(x, we0, we1, we2, out);
}

// round 13
// speedup vs baseline: 2.1246x; 1.0238x over previous
#include <cuda_runtime.h>

// Problem constants
#define N_ROWS   1344              // B*C = 64*21
#define R_WIN    32                // windows per row (L/MAX_PL = 1024/32)
#define NWIN     (N_ROWS * R_WIN)  // 43008
#define DM       512               // D_MODEL
#define TGT      4                 // MAX_PL/MIN_PL
#define PE_LEN   128               // R_WIN * TGT
#define MAIN_OUT ((long long)N_ROWS * PE_LEN * DM)  // 88080384
#define CLS_BLOCKS (NWIN / 128)    // 336 blocks x 128 threads (1 thread/window)

typedef unsigned long long u64;

// f32x2 packed helpers (sm_103a FFMA2 — PTX-only form).
__device__ __forceinline__ u64 fma2(u64 a, u64 b, u64 c) {
    u64 d; asm("fma.rn.f32x2 %0, %1, %2, %3;" : "=l"(d) : "l"(a), "l"(b), "l"(c));
    return d;
}
__device__ __forceinline__ u64 mul2(u64 a, u64 b) {
    u64 d; asm("mul.rn.f32x2 %0, %1, %2;" : "=l"(d) : "l"(a), "l"(b));
    return d;
}
__device__ __forceinline__ u64 add2(u64 a, u64 b) {
    u64 d; asm("add.rn.f32x2 %0, %1, %2;" : "=l"(d) : "l"(a), "l"(b));
    return d;
}
__device__ __forceinline__ float hadd2(u64 a) {
    float lo, hi;
    asm("mov.b64 {%0, %1}, %2;" : "=f"(lo), "=f"(hi) : "l"(a));
    return lo + hi;
}

// Scratch: packed preds, 2 bits per window via two ballot words per n.
__device__ uint2 g_predpk[N_ROWS];

// ---------------------------------------------------------------------------
// Kernel 1: classifier + tail fill (R9's proven version, ballot-packed preds).
// ---------------------------------------------------------------------------
__global__ void __launch_bounds__(128)
pre_kernel(const float* __restrict__ x,
           const float* __restrict__ w1,
           const float* __restrict__ b1,
           const float* __restrict__ w2,
           const float* __restrict__ b2,
           float* __restrict__ out,
           long long tail_start, long long total) {
    int bid = blockIdx.x;
    if (bid >= CLS_BLOCKS) {
        long long i = tail_start + (long long)(bid - CLS_BLOCKS) * 128 + threadIdx.x;
        if (i < total) out[i] = 21.0f;   // reference returns (x_patch, C=21)
        return;
    }

    __shared__ __align__(16) float s_w1[64 * 32];   // 8 KB
    __shared__ __align__(16) float s_w2[192];
    __shared__ float s_b1[64];
    __shared__ float s_b2[3];

    const int tid = threadIdx.x;

    {
        const float4* g = (const float4*)w1;
        float4* sm = (float4*)s_w1;
#pragma unroll
        for (int i = 0; i < 4; i++) sm[tid + 128 * i] = g[tid + 128 * i];
        if (tid < 48) ((float4*)s_w2)[tid] = ((const float4*)w2)[tid];
        if (tid < 64) s_b1[tid] = b1[tid];
        if (tid < 3)  s_b2[tid] = b2[tid];
    }
    __syncthreads();

    const int w = bid * 128 + tid;

    const float4* xw = (const float4*)(x + (size_t)w * 32);
    float4 xv[8];
#pragma unroll
    for (int i = 0; i < 8; i++) xv[i] = xw[i];

    float l0 = s_b2[0], l1 = s_b2[1], l2 = s_b2[2];

#pragma unroll 4
    for (int h = 0; h < 64; h++) {
        const float4* wr = (const float4*)(s_w1 + h * 32);   // broadcast LDS
        float a0 = 0.f, a1 = 0.f, a2 = 0.f, a3 = 0.f;
#pragma unroll
        for (int i = 0; i < 8; i++) {
            float4 wv = wr[i];
            a0 = fmaf(wv.x, xv[i].x, a0);
            a1 = fmaf(wv.y, xv[i].y, a1);
            a2 = fmaf(wv.z, xv[i].z, a2);
            a3 = fmaf(wv.w, xv[i].w, a3);
        }
        float hv = s_b1[h] + ((a0 + a1) + (a2 + a3));
        hv = fmaxf(hv, 0.0f);
        l0 = fmaf(s_w2[h], hv, l0);
        l1 = fmaf(s_w2[64 + h], hv, l1);
        l2 = fmaf(s_w2[128 + h], hv, l2);
    }

    int p = 0;
    float m = l0;
    if (l1 > m) { m = l1; p = 1; }   // strict > = first-max (jnp.argmax)
    if (l2 > m) { m = l2; p = 2; }

    unsigned pb0 = __ballot_sync(0xffffffffu, p & 1);
    unsigned pb1 = __ballot_sync(0xffffffffu, p & 2);
    if ((tid & 31) == 0) g_predpk[w >> 5] = make_uint2(pb0, pb1);
}

// ---------------------------------------------------------------------------
// Kernel 2: embedding + repeat + PE + store — two dims per thread (2t, 2t+1),
// window loop UNROLLED x2 so the compiler interleaves two independent
// windows' LDS + dot chains (the R12 profile showed 37.7% issue with the
// loop forced to unroll 1 — per-window dependency latency was exposed).
// Natural regs ~200-230 -> still 2 CTAs at 128 thr (<=256 regs), 8 warps/SM.
// ---------------------------------------------------------------------------
__global__ void __launch_bounds__(128)
emb_kernel(const float* __restrict__ x,
           const float* __restrict__ we0,   // [512][8]
           const float* __restrict__ we1,   // [512][16]
           const float* __restrict__ we2,   // [512][32]
           float* __restrict__ out) {
    __shared__ __align__(16) float s_x[R_WIN * 32];   // 4 KB

    const int tid  = threadIdx.x;
    const int n    = blockIdx.x >> 1;
    const int dblk = (blockIdx.x & 1) << 8;
    const int d0   = dblk + 2 * tid;     // even dim; odd dim = d0 + 1

    // Weight cache for BOTH dims, packed pairs. [j][...] j=0 even, j=1 odd.
    u64 w0r[2][4], w1r[2][8], w2r[2][16];
#pragma unroll
    for (int j = 0; j < 2; j++) {
        int dd = d0 + j;
        const ulonglong2* p0 = (const ulonglong2*)(we0 + dd * 8);
#pragma unroll
        for (int i = 0; i < 2; i++) { ulonglong2 v = p0[i]; w0r[j][2*i] = v.x; w0r[j][2*i+1] = v.y; }
        const ulonglong2* p1 = (const ulonglong2*)(we1 + dd * 16);
#pragma unroll
        for (int i = 0; i < 4; i++) { ulonglong2 v = p1[i]; w1r[j][2*i] = v.x; w1r[j][2*i+1] = v.y; }
        const ulonglong2* p2 = (const ulonglong2*)(we2 + dd * 32);
#pragma unroll
        for (int i = 0; i < 8; i++) { ulonglong2 v = p2[i]; w2r[j][2*i] = v.x; w2r[j][2*i+1] = v.y; }
    }

    // Cooperative x-row staging (128 threads x 2 float4 = 1024 floats).
    {
        const float4* xg = (const float4*)(x + (size_t)n * 1024);
        ((float4*)s_x)[tid]       = xg[tid];
        ((float4*)s_x)[tid + 128] = xg[tid + 128];
    }
    const uint2 pb = g_predpk[n];

    // PE setup — ONE frequency for the pair (d0 even).
    const float kLn = -9.21034037197618f / (float)DM;   // -ln(10000)/512
    float delta = expf((float)d0 * kLn);
    float s1, c1;
    sincosf(delta, &s1, &c1);
    float s2 = 2.0f * s1 * c1;
    float c2 = fmaf(c1, c1, -s1 * s1);
    float s3 = fmaf(s1, c2, c1 * s2);
    float c3 = fmaf(c1, c2, -s1 * s2);
    float s4 = 2.0f * s2 * c2;
    float c4 = fmaf(c2, c2, -s2 * s2);
    float s = 0.0f, c = 1.0f;           // state at pos 0

    __syncthreads();

    float* o = out + (size_t)n * (PE_LEN * DM) + d0;

#pragma unroll 2
    for (int w = 0; w < R_WIN; w++) {
        int pred = ((pb.x >> w) & 1u) | (((pb.y >> w) & 1u) << 1);

        const ulonglong2* xq2 = (const ulonglong2*)(s_x + w * 32);
        u64 xv[16];
#pragma unroll
        for (int i = 0; i < 8; i++) { ulonglong2 v = xq2[i]; xv[2*i] = v.x; xv[2*i+1] = v.y; }

        // vE[k] (even dim), vO[k] (odd dim) for positions k=0..3.
        float vE0, vE1, vE2, vE3, vO0, vO1, vO2, vO3;
        if (pred == 0) {
            // 4 patches of 8 floats; repeat idx = [0,1,2,3]
            float aE[4], aO[4];
#pragma unroll
            for (int k = 0; k < 4; k++) {
                u64 aa = mul2(w0r[0][0], xv[4*k]);
                aa = fma2(w0r[0][1], xv[4*k+1], aa);
                aa = fma2(w0r[0][2], xv[4*k+2], aa);
                aa = fma2(w0r[0][3], xv[4*k+3], aa);
                aE[k] = hadd2(aa);
                u64 bb = mul2(w0r[1][0], xv[4*k]);
                bb = fma2(w0r[1][1], xv[4*k+1], bb);
                bb = fma2(w0r[1][2], xv[4*k+2], bb);
                bb = fma2(w0r[1][3], xv[4*k+3], bb);
                aO[k] = hadd2(bb);
            }
            vE0 = aE[0]; vE1 = aE[1]; vE2 = aE[2]; vE3 = aE[3];
            vO0 = aO[0]; vO1 = aO[1]; vO2 = aO[2]; vO3 = aO[3];
        } else if (pred == 1) {
            // 2 patches of 16 floats; repeat idx = [0,0,0,1]
            float hE[2], hO[2];
#pragma unroll
            for (int half = 0; half < 2; half++) {
                const u64* xh = xv + 8 * half;
                u64 a0 = mul2(w1r[0][0], xh[0]);
                u64 a1 = mul2(w1r[0][1], xh[1]);
                u64 b0 = mul2(w1r[1][0], xh[0]);
                u64 b1 = mul2(w1r[1][1], xh[1]);
#pragma unroll
                for (int i = 2; i < 8; i += 2) {
                    a0 = fma2(w1r[0][i],   xh[i],   a0);
                    a1 = fma2(w1r[0][i+1], xh[i+1], a1);
                    b0 = fma2(w1r[1][i],   xh[i],   b0);
                    b1 = fma2(w1r[1][i+1], xh[i+1], b1);
                }
                hE[half] = hadd2(add2(a0, a1));
                hO[half] = hadd2(add2(b0, b1));
            }
            vE0 = hE[0]; vE1 = hE[0]; vE2 = hE[0]; vE3 = hE[1];
            vO0 = hO[0]; vO1 = hO[0]; vO2 = hO[0]; vO3 = hO[1];
        } else {
            // 1 patch of 32 floats -> replicated 4x
            u64 a0 = mul2(w2r[0][0], xv[0]);
            u64 a1 = mul2(w2r[0][1], xv[1]);
            u64 b0 = mul2(w2r[1][0], xv[0]);
            u64 b1 = mul2(w2r[1][1], xv[1]);
#pragma unroll
            for (int i = 2; i < 16; i += 2) {
                a0 = fma2(w2r[0][i],   xv[i],   a0);
                a1 = fma2(w2r[0][i+1], xv[i+1], a1);
                b0 = fma2(w2r[1][i],   xv[i],   b0);
                b1 = fma2(w2r[1][i+1], xv[i+1], b1);
            }
            float ce = hadd2(add2(a0, a1));
            float co = hadd2(add2(b0, b1));
            vE0 = ce; vE1 = ce; vE2 = ce; vE3 = ce;
            vO0 = co; vO1 = co; vO2 = co; vO3 = co;
        }

        // PE: one rotation state serves both dims (even: +sin, odd: +cos).
        float sn1 = fmaf(s, c1, c * s1), co1 = fmaf(c, c1, -s * s1);
        float sn2 = fmaf(s, c2, c * s2), co2 = fmaf(c, c2, -s * s2);
        float sn3 = fmaf(s, c3, c * s3), co3 = fmaf(c, c3, -s * s3);

        *(float2*)(o + 0 * DM) = make_float2(vE0 + s,   vO0 + c);
        *(float2*)(o + 1 * DM) = make_float2(vE1 + sn1, vO1 + co1);
        *(float2*)(o + 2 * DM) = make_float2(vE2 + sn2, vO2 + co2);
        *(float2*)(o + 3 * DM) = make_float2(vE3 + sn3, vO3 + co3);

        // Advance base angle by 4*Delta.
        float ns = fmaf(s, c4, c * s4);
        c = fmaf(c, c4, -s * s4);
        s = ns;

        o += TGT * DM;
    }
}

extern "C" void kernel_launch(void* const* d_in, const int* in_sizes, int n_in,
                              void* d_out, int out_size) {
    const float* x   = (const float*)d_in[0];
    const float* w1  = (const float*)d_in[1];
    const float* b1  = (const float*)d_in[2];
    const float* w2  = (const float*)d_in[3];
    const float* b2  = (const float*)d_in[4];
    const float* we0 = (const float*)d_in[5];
    const float* we1 = (const float*)d_in[6];
    const float* we2 = (const float*)d_in[7];
    float* out = (float*)d_out;

    long long total = (long long)out_size;
    long long tail  = (total > MAIN_OUT) ? (total - MAIN_OUT) : 0;
    int tail_blocks = (int)((tail + 127) / 128);

    pre_kernel<<<CLS_BLOCKS + tail_blocks, 128>>>(x, w1, b1, w2, b2,
                                                  out, MAIN_OUT, total);
    emb_kernel<<<N_ROWS * 2, 128>>>(x, we0, we1, we2, out);
}